// round 2
// baseline (speedup 1.0000x reference)
#include <cuda_runtime.h>
#include <cuda_bf16.h>
#include <math.h>

#define N_NODES 100000
#define NFEAT   512
#define NHID    256
#define NCLASS  40
#define NEDGE   1600000
#define KHOPS   10
#define ALPHA_F 0.1f

// ---------------- scratch (device globals; no allocs allowed) ----------------
__device__ float g_h [(size_t)N_NODES * NHID];    // 102.4 MB
__device__ float g_h2[(size_t)N_NODES * NCLASS];  // 16 MB
__device__ float g_za[(size_t)N_NODES * NCLASS];  // 16 MB
__device__ float g_ev[NEDGE];                     // 6.4 MB (pre-scaled edge vals)

// ---------------- GEMM1: h = relu(x @ W1 + b1), [100000,512]x[512,256] -------
// Classic SIMT sgemm: 128x128 block tile, BK=8, 256 threads, 8x8 microtile.
#define BM 128
#define BN 128
#define BK 8

__global__ void __launch_bounds__(256, 2)
gemm1_kernel(const float* __restrict__ x, const float* __restrict__ W1,
             const float* __restrict__ b1, float* __restrict__ h)
{
    __shared__ float As[BK][BM + 4];
    __shared__ float Bs[BK][BN];

    const int tid = threadIdx.x;
    const int m0 = blockIdx.x * BM;
    const int n0 = blockIdx.y * BN;

    // A tile loads: 128 rows x 8 cols = 256 float4, 1 per thread
    const int ar = tid >> 1;            // 0..127
    const int ac = (tid & 1) << 2;      // 0 or 4
    // B tile loads: 8 rows x 128 cols = 256 float4, 1 per thread
    const int br = tid >> 5;            // 0..7
    const int bc = (tid & 31) << 2;     // 0..124

    const int tm = (tid >> 4) << 3;     // 0..120
    const int tn = (tid & 15) << 3;     // 0..120

    const int arow_g = min(m0 + ar, N_NODES - 1);

    float acc[8][8];
    #pragma unroll
    for (int i = 0; i < 8; i++)
        #pragma unroll
        for (int j = 0; j < 8; j++) acc[i][j] = 0.f;

    for (int k0 = 0; k0 < NFEAT; k0 += BK) {
        float4 av = *(const float4*)&x[(size_t)arow_g * NFEAT + k0 + ac];
        float4 bv = *(const float4*)&W1[(size_t)(k0 + br) * NHID + n0 + bc];
        As[ac + 0][ar] = av.x;
        As[ac + 1][ar] = av.y;
        As[ac + 2][ar] = av.z;
        As[ac + 3][ar] = av.w;
        *(float4*)&Bs[br][bc] = bv;
        __syncthreads();

        #pragma unroll
        for (int k = 0; k < BK; k++) {
            float a[8], b[8];
            *(float4*)(a)     = *(const float4*)&As[k][tm];
            *(float4*)(a + 4) = *(const float4*)&As[k][tm + 4];
            *(float4*)(b)     = *(const float4*)&Bs[k][tn];
            *(float4*)(b + 4) = *(const float4*)&Bs[k][tn + 4];
            #pragma unroll
            for (int i = 0; i < 8; i++)
                #pragma unroll
                for (int j = 0; j < 8; j++)
                    acc[i][j] = fmaf(a[i], b[j], acc[i][j]);
        }
        __syncthreads();
    }

    float bb[8];
    #pragma unroll
    for (int j = 0; j < 8; j++) bb[j] = b1[n0 + tn + j];

    #pragma unroll
    for (int i = 0; i < 8; i++) {
        int row = m0 + tm + i;
        if (row < N_NODES) {
            #pragma unroll
            for (int j = 0; j < 8; j += 4) {
                float4 o;
                o.x = fmaxf(acc[i][j + 0] + bb[j + 0], 0.f);
                o.y = fmaxf(acc[i][j + 1] + bb[j + 1], 0.f);
                o.z = fmaxf(acc[i][j + 2] + bb[j + 2], 0.f);
                o.w = fmaxf(acc[i][j + 3] + bb[j + 3], 0.f);
                *(float4*)&h[(size_t)row * NHID + n0 + tn + j] = o;
            }
        }
    }
}

// ---------------- GEMM2: h2 = h @ W2 + b2, [100000,256]x[256,40] -------------
__global__ void __launch_bounds__(256, 2)
gemm2_kernel(const float* __restrict__ h, const float* __restrict__ W2,
             const float* __restrict__ b2, float* __restrict__ h2)
{
    __shared__ float hs[128][65];      // pad 65 -> conflict-free column reads
    __shared__ float w2s[64][NCLASS];

    const int tid = threadIdx.x;
    const int r0 = blockIdx.x * 128;
    const int row = tid >> 1;
    const int half = tid & 1;

    float acc[20];
    #pragma unroll
    for (int j = 0; j < 20; j++) acc[j] = 0.f;

    for (int k0 = 0; k0 < NHID; k0 += 64) {
        #pragma unroll
        for (int i = 0; i < 8; i++) {
            int t = tid + i * 256;
            int rr = t >> 4;               // 0..127
            int cc = (t & 15) << 2;        // 0..60
            int gr = min(r0 + rr, N_NODES - 1);
            float4 v = *(const float4*)&h[(size_t)gr * NHID + k0 + cc];
            hs[rr][cc + 0] = v.x;
            hs[rr][cc + 1] = v.y;
            hs[rr][cc + 2] = v.z;
            hs[rr][cc + 3] = v.w;
        }
        for (int t = tid; t < 640; t += 256) {
            int wr = t / 10;
            int wc = (t - wr * 10) << 2;
            *(float4*)&w2s[wr][wc] = *(const float4*)&W2[(size_t)(k0 + wr) * NCLASS + wc];
        }
        __syncthreads();

        #pragma unroll 8
        for (int k = 0; k < 64; k++) {
            float hv = hs[row][k];
            #pragma unroll
            for (int j5 = 0; j5 < 5; j5++) {
                float4 w = *(const float4*)&w2s[k][half * 20 + j5 * 4];
                acc[j5 * 4 + 0] = fmaf(hv, w.x, acc[j5 * 4 + 0]);
                acc[j5 * 4 + 1] = fmaf(hv, w.y, acc[j5 * 4 + 1]);
                acc[j5 * 4 + 2] = fmaf(hv, w.z, acc[j5 * 4 + 2]);
                acc[j5 * 4 + 3] = fmaf(hv, w.w, acc[j5 * 4 + 3]);
            }
        }
        __syncthreads();
    }

    const int gr = r0 + row;
    if (gr < N_NODES) {
        #pragma unroll
        for (int j5 = 0; j5 < 5; j5++) {
            float4 o;
            o.x = acc[j5 * 4 + 0] + b2[half * 20 + j5 * 4 + 0];
            o.y = acc[j5 * 4 + 1] + b2[half * 20 + j5 * 4 + 1];
            o.z = acc[j5 * 4 + 2] + b2[half * 20 + j5 * 4 + 2];
            o.w = acc[j5 * 4 + 3] + b2[half * 20 + j5 * 4 + 3];
            *(float4*)&h2[(size_t)gr * NCLASS + half * 20 + j5 * 4] = o;
        }
    }
}

// ---------------- edge-value pre-scale: ev = (1-alpha) * edge_val ------------
__global__ void __launch_bounds__(256)
edge_scale_kernel(const float* __restrict__ eval_, float* __restrict__ ev)
{
    int i = blockIdx.x * 256 + threadIdx.x;
    const int n4 = NEDGE / 4;
    if (i < n4) {
        float4 v = ((const float4*)eval_)[i];
        const float s = 1.0f - ALPHA_F;
        v.x *= s; v.y *= s; v.z *= s; v.w *= s;
        ((float4*)ev)[i] = v;
    }
}

// ---------------- propagation: zout = ALPHA*h2  (then edges scatter in) ------
__global__ void __launch_bounds__(256)
scale_init_kernel(const float* __restrict__ h2, float* __restrict__ zout)
{
    int i = blockIdx.x * 256 + threadIdx.x;
    const int n4 = N_NODES * NCLASS / 4;
    if (i < n4) {
        float4 v = ((const float4*)h2)[i];
        v.x *= ALPHA_F; v.y *= ALPHA_F; v.z *= ALPHA_F; v.w *= ALPHA_F;
        ((float4*)zout)[i] = v;
    }
}

// zout[dst] += ev[e] * zin[src]; thread = (edge, 4-class group)
__global__ void __launch_bounds__(256)
edge_kernel(const int* __restrict__ esrc, const int* __restrict__ edst,
            const float* __restrict__ ev, const float* __restrict__ zin,
            float* __restrict__ zout)
{
    unsigned idx = blockIdx.x * 256u + threadIdx.x;   // E*10 = 16M threads
    if (idx >= (unsigned)NEDGE * 10u) return;
    unsigned e = idx / 10u;
    unsigned g = idx - e * 10u;
    int s = esrc[e];
    int d = edst[e];
    float v = ev[e];
    float4 z = *(const float4*)&zin[(size_t)s * NCLASS + g * 4];
    float* p = &zout[(size_t)d * NCLASS + g * 4];
    asm volatile("red.global.add.v4.f32 [%0], {%1, %2, %3, %4};"
                 :: "l"(p), "f"(v * z.x), "f"(v * z.y), "f"(v * z.z), "f"(v * z.w)
                 : "memory");
}

// ---------------- log_softmax per row (one warp / row, in-place OK) ----------
__global__ void __launch_bounds__(256)
softmax_kernel(const float* __restrict__ z, float* __restrict__ out)
{
    int row = blockIdx.x * 8 + (threadIdx.x >> 5);
    int lane = threadIdx.x & 31;
    if (row >= N_NODES) return;
    const float* zr = z + (size_t)row * NCLASS;
    float v0 = zr[lane];
    bool has2 = (lane + 32) < NCLASS;
    float v1 = has2 ? zr[lane + 32] : -3.402823466e38f;
    float m = fmaxf(v0, v1);
    #pragma unroll
    for (int o = 16; o > 0; o >>= 1) m = fmaxf(m, __shfl_xor_sync(0xffffffffu, m, o));
    float s = __expf(v0 - m) + (has2 ? __expf(v1 - m) : 0.f);
    #pragma unroll
    for (int o = 16; o > 0; o >>= 1) s += __shfl_xor_sync(0xffffffffu, s, o);
    float lse = m + __logf(s);
    float* orow = out + (size_t)row * NCLASS;
    orow[lane] = v0 - lse;
    if (has2) orow[lane + 32] = v1 - lse;
}

// ---------------- launch ----------------
extern "C" void kernel_launch(void* const* d_in, const int* in_sizes, int n_in,
                              void* d_out, int out_size)
{
    const float* x     = (const float*)d_in[0];
    const int*   esrc  = (const int*)  d_in[1];
    const int*   edst  = (const int*)  d_in[2];
    const float* eval_ = (const float*)d_in[3];
    const float* W1    = (const float*)d_in[4];
    const float* b1    = (const float*)d_in[5];
    const float* W2    = (const float*)d_in[6];
    const float* b2    = (const float*)d_in[7];
    float* out = (float*)d_out;

    float *h, *h2, *za, *ev;
    cudaGetSymbolAddress((void**)&h,  g_h);
    cudaGetSymbolAddress((void**)&h2, g_h2);
    cudaGetSymbolAddress((void**)&za, g_za);
    cudaGetSymbolAddress((void**)&ev, g_ev);

    dim3 g1((N_NODES + BM - 1) / BM, NHID / BN);   // (782, 2)
    gemm1_kernel<<<g1, 256>>>(x, W1, b1, h);
    gemm2_kernel<<<(N_NODES + 127) / 128, 256>>>(h, W2, b2, h2);
    edge_scale_kernel<<<(NEDGE / 4 + 255) / 256, 256>>>(eval_, ev);

    const int init_blocks = (N_NODES * NCLASS / 4 + 255) / 256;
    const int edge_blocks = (int)(((unsigned)NEDGE * 10u + 255u) / 256u);

    const float* zin = h2;
    for (int i = 0; i < KHOPS; i++) {
        float* zout = (i % 2 == 0) ? za : out;   // last iter (i=9) writes `out`
        scale_init_kernel<<<init_blocks, 256>>>(h2, zout);
        edge_kernel<<<edge_blocks, 256>>>(esrc, edst, ev, zin, zout);
        zin = zout;
    }

    softmax_kernel<<<(N_NODES + 7) / 8, 256>>>(out, out);
}

// round 3
// speedup vs baseline: 1.4685x; 1.4685x over previous
#include <cuda_runtime.h>
#include <cuda_bf16.h>
#include <cstdint>
#include <math.h>

#define N_NODES 100000
#define NFEAT   512
#define NHID    256
#define NCLASS  40
#define NEDGE   1600000
#define KHOPS   10
#define ALPHA_F 0.1f

// ---------------- scratch (device globals; no allocs allowed) ----------------
__device__ float g_h [(size_t)N_NODES * NHID];    // 102.4 MB
__device__ float g_h2[(size_t)N_NODES * NCLASS];  // 16 MB
__device__ float g_za[(size_t)N_NODES * NCLASS];  // 16 MB
__device__ float g_ev[NEDGE];                     // 6.4 MB (pre-scaled edge vals)

// ---------------- cp.async helpers ----------------
__device__ __forceinline__ void cp_async16(uint32_t saddr, const void* gaddr) {
    asm volatile("cp.async.cg.shared.global [%0], [%1], 16;\n" :: "r"(saddr), "l"(gaddr));
}
__device__ __forceinline__ void cp_commit() {
    asm volatile("cp.async.commit_group;\n" ::: "memory");
}
__device__ __forceinline__ void cp_wait1() {
    asm volatile("cp.async.wait_group 1;\n" ::: "memory");
}

// ---------------- GEMM1: h = relu(x @ W1 + b1) via tf32 mma.sync -------------
// Block 128x128, BK=16, 256 threads (8 warps, 2x4 -> warp tile 64x32),
// cp.async double-buffered smem. fp32 bits fed to tf32 mma (HW truncation).
#define G1_BK      16
#define G1_ASTRIDE 20    // 16 + 4 pad: conflict-free A fragment reads
#define G1_BSTRIDE 136   // 128 + 8 pad: conflict-free B fragment reads

__global__ void __launch_bounds__(256, 2)
gemm1_tf32_kernel(const float* __restrict__ x, const float* __restrict__ W1,
                  const float* __restrict__ b1, float* __restrict__ h)
{
    __shared__ float As[2][128][G1_ASTRIDE];   // [buf][m][k] 20.5 KB
    __shared__ float Bs[2][G1_BK][G1_BSTRIDE]; // [buf][k][n] 17.4 KB

    const int tid  = threadIdx.x;
    const int warp = tid >> 5;
    const int lane = tid & 31;
    const int grp  = lane >> 2;   // 0..7
    const int tig  = lane & 3;    // 0..3
    const int warp_m = warp & 1;  // 0..1
    const int warp_n = warp >> 1; // 0..3

    const int m0 = blockIdx.x * 128;
    const int n0 = blockIdx.y * 128;

    const uint32_t sA = (uint32_t)__cvta_generic_to_shared(&As[0][0][0]);
    const uint32_t sB = (uint32_t)__cvta_generic_to_shared(&Bs[0][0][0]);

    float acc[4][4][4];
    #pragma unroll
    for (int i = 0; i < 4; i++)
        #pragma unroll
        for (int j = 0; j < 4; j++)
            #pragma unroll
            for (int r = 0; r < 4; r++) acc[i][j][r] = 0.f;

    // Loader indices: A tile 128x16 = 512 x 16B chunks; B tile 16x128 = 512 chunks.
    const int ac0 = tid, ac1 = tid + 256;
    const int ar0 = ac0 >> 2, akc0 = (ac0 & 3) << 2;
    const int ar1 = ac1 >> 2, akc1 = (ac1 & 3) << 2;
    const int gr0 = min(m0 + ar0, N_NODES - 1);
    const int gr1 = min(m0 + ar1, N_NODES - 1);
    const int br0 = ac0 >> 5, bnc0 = (ac0 & 31) << 2;
    const int br1 = ac1 >> 5, bnc1 = (ac1 & 31) << 2;

    const int NT = NFEAT / G1_BK;  // 32

    // prologue: tile 0 -> buf 0
    {
        const int k0 = 0;
        cp_async16(sA + (uint32_t)(((0*128 + ar0) * G1_ASTRIDE + akc0) * 4),
                   &x[(size_t)gr0 * NFEAT + k0 + akc0]);
        cp_async16(sA + (uint32_t)(((0*128 + ar1) * G1_ASTRIDE + akc1) * 4),
                   &x[(size_t)gr1 * NFEAT + k0 + akc1]);
        cp_async16(sB + (uint32_t)(((0*G1_BK + br0) * G1_BSTRIDE + bnc0) * 4),
                   &W1[(size_t)(k0 + br0) * NHID + n0 + bnc0]);
        cp_async16(sB + (uint32_t)(((0*G1_BK + br1) * G1_BSTRIDE + bnc1) * 4),
                   &W1[(size_t)(k0 + br1) * NHID + n0 + bnc1]);
        cp_commit();
    }

    for (int kt = 0; kt < NT; kt++) {
        if (kt + 1 < NT) {
            const int k0 = (kt + 1) * G1_BK;
            const int nb = (kt + 1) & 1;
            cp_async16(sA + (uint32_t)(((nb*128 + ar0) * G1_ASTRIDE + akc0) * 4),
                       &x[(size_t)gr0 * NFEAT + k0 + akc0]);
            cp_async16(sA + (uint32_t)(((nb*128 + ar1) * G1_ASTRIDE + akc1) * 4),
                       &x[(size_t)gr1 * NFEAT + k0 + akc1]);
            cp_async16(sB + (uint32_t)(((nb*G1_BK + br0) * G1_BSTRIDE + bnc0) * 4),
                       &W1[(size_t)(k0 + br0) * NHID + n0 + bnc0]);
            cp_async16(sB + (uint32_t)(((nb*G1_BK + br1) * G1_BSTRIDE + bnc1) * 4),
                       &W1[(size_t)(k0 + br1) * NHID + n0 + bnc1]);
        }
        cp_commit();
        cp_wait1();          // tile kt resident
        __syncthreads();

        const int buf = kt & 1;
        #pragma unroll
        for (int ks = 0; ks < 2; ks++) {
            const int kb = ks * 8;
            uint32_t a[4][4], b[4][2];
            #pragma unroll
            for (int mf = 0; mf < 4; mf++) {
                const int r = warp_m * 64 + mf * 16 + grp;
                a[mf][0] = __float_as_uint(As[buf][r    ][kb + tig    ]);
                a[mf][1] = __float_as_uint(As[buf][r + 8][kb + tig    ]);
                a[mf][2] = __float_as_uint(As[buf][r    ][kb + tig + 4]);
                a[mf][3] = __float_as_uint(As[buf][r + 8][kb + tig + 4]);
            }
            #pragma unroll
            for (int nf = 0; nf < 4; nf++) {
                const int cn = warp_n * 32 + nf * 8 + grp;
                b[nf][0] = __float_as_uint(Bs[buf][kb + tig    ][cn]);
                b[nf][1] = __float_as_uint(Bs[buf][kb + tig + 4][cn]);
            }
            #pragma unroll
            for (int mf = 0; mf < 4; mf++)
                #pragma unroll
                for (int nf = 0; nf < 4; nf++) {
                    asm volatile(
                        "mma.sync.aligned.m16n8k8.row.col.f32.tf32.tf32.f32 "
                        "{%0,%1,%2,%3}, {%4,%5,%6,%7}, {%8,%9}, {%0,%1,%2,%3};\n"
                        : "+f"(acc[mf][nf][0]), "+f"(acc[mf][nf][1]),
                          "+f"(acc[mf][nf][2]), "+f"(acc[mf][nf][3])
                        : "r"(a[mf][0]), "r"(a[mf][1]), "r"(a[mf][2]), "r"(a[mf][3]),
                          "r"(b[nf][0]), "r"(b[nf][1]));
                }
        }
        __syncthreads();
    }

    // epilogue: bias + relu, float2 stores
    #pragma unroll
    for (int nf = 0; nf < 4; nf++) {
        const int cg = n0 + warp_n * 32 + nf * 8 + 2 * tig;
        const float bx = b1[cg], by = b1[cg + 1];
        #pragma unroll
        for (int mf = 0; mf < 4; mf++) {
            const int rg = m0 + warp_m * 64 + mf * 16 + grp;
            if (rg < N_NODES) {
                float2 o;
                o.x = fmaxf(acc[mf][nf][0] + bx, 0.f);
                o.y = fmaxf(acc[mf][nf][1] + by, 0.f);
                *(float2*)&h[(size_t)rg * NHID + cg] = o;
            }
            if (rg + 8 < N_NODES) {
                float2 o;
                o.x = fmaxf(acc[mf][nf][2] + bx, 0.f);
                o.y = fmaxf(acc[mf][nf][3] + by, 0.f);
                *(float2*)&h[(size_t)(rg + 8) * NHID + cg] = o;
            }
        }
    }
}

// ---------------- GEMM2: h2 = h @ W2 + b2, [100000,256]x[256,40] -------------
__global__ void __launch_bounds__(256, 2)
gemm2_kernel(const float* __restrict__ h, const float* __restrict__ W2,
             const float* __restrict__ b2, float* __restrict__ h2)
{
    __shared__ float hs[128][65];
    __shared__ float w2s[64][NCLASS];

    const int tid = threadIdx.x;
    const int r0 = blockIdx.x * 128;
    const int row = tid >> 1;
    const int half = tid & 1;

    float acc[20];
    #pragma unroll
    for (int j = 0; j < 20; j++) acc[j] = 0.f;

    for (int k0 = 0; k0 < NHID; k0 += 64) {
        #pragma unroll
        for (int i = 0; i < 8; i++) {
            int t = tid + i * 256;
            int rr = t >> 4;
            int cc = (t & 15) << 2;
            int gr = min(r0 + rr, N_NODES - 1);
            float4 v = *(const float4*)&h[(size_t)gr * NHID + k0 + cc];
            hs[rr][cc + 0] = v.x;
            hs[rr][cc + 1] = v.y;
            hs[rr][cc + 2] = v.z;
            hs[rr][cc + 3] = v.w;
        }
        for (int t = tid; t < 640; t += 256) {
            int wr = t / 10;
            int wc = (t - wr * 10) << 2;
            *(float4*)&w2s[wr][wc] = *(const float4*)&W2[(size_t)(k0 + wr) * NCLASS + wc];
        }
        __syncthreads();

        #pragma unroll 8
        for (int k = 0; k < 64; k++) {
            float hv = hs[row][k];
            #pragma unroll
            for (int j5 = 0; j5 < 5; j5++) {
                float4 w = *(const float4*)&w2s[k][half * 20 + j5 * 4];
                acc[j5 * 4 + 0] = fmaf(hv, w.x, acc[j5 * 4 + 0]);
                acc[j5 * 4 + 1] = fmaf(hv, w.y, acc[j5 * 4 + 1]);
                acc[j5 * 4 + 2] = fmaf(hv, w.z, acc[j5 * 4 + 2]);
                acc[j5 * 4 + 3] = fmaf(hv, w.w, acc[j5 * 4 + 3]);
            }
        }
        __syncthreads();
    }

    const int gr = r0 + row;
    if (gr < N_NODES) {
        #pragma unroll
        for (int j5 = 0; j5 < 5; j5++) {
            float4 o;
            o.x = acc[j5 * 4 + 0] + b2[half * 20 + j5 * 4 + 0];
            o.y = acc[j5 * 4 + 1] + b2[half * 20 + j5 * 4 + 1];
            o.z = acc[j5 * 4 + 2] + b2[half * 20 + j5 * 4 + 2];
            o.w = acc[j5 * 4 + 3] + b2[half * 20 + j5 * 4 + 3];
            *(float4*)&h2[(size_t)gr * NCLASS + half * 20 + j5 * 4] = o;
        }
    }
}

// ---------------- edge-value pre-scale: ev = (1-alpha) * edge_val ------------
__global__ void __launch_bounds__(256)
edge_scale_kernel(const float* __restrict__ eval_, float* __restrict__ ev)
{
    int i = blockIdx.x * 256 + threadIdx.x;
    const int n4 = NEDGE / 4;
    if (i < n4) {
        float4 v = ((const float4*)eval_)[i];
        const float s = 1.0f - ALPHA_F;
        v.x *= s; v.y *= s; v.z *= s; v.w *= s;
        ((float4*)ev)[i] = v;
    }
}

// ---------------- propagation: zout = ALPHA*h2  (then edges scatter in) ------
__global__ void __launch_bounds__(256)
scale_init_kernel(const float* __restrict__ h2, float* __restrict__ zout)
{
    int i = blockIdx.x * 256 + threadIdx.x;
    const int n4 = N_NODES * NCLASS / 4;
    if (i < n4) {
        float4 v = ((const float4*)h2)[i];
        v.x *= ALPHA_F; v.y *= ALPHA_F; v.z *= ALPHA_F; v.w *= ALPHA_F;
        ((float4*)zout)[i] = v;
    }
}

// zout[dst] += ev[e] * zin[src]; thread = (edge, 4-class group)
__global__ void __launch_bounds__(256)
edge_kernel(const int* __restrict__ esrc, const int* __restrict__ edst,
            const float* __restrict__ ev, const float* __restrict__ zin,
            float* __restrict__ zout)
{
    unsigned idx = blockIdx.x * 256u + threadIdx.x;   // E*10 = 16M threads
    if (idx >= (unsigned)NEDGE * 10u) return;
    unsigned e = idx / 10u;
    unsigned g = idx - e * 10u;
    int s = esrc[e];
    int d = edst[e];
    float v = ev[e];
    float4 z = *(const float4*)&zin[(size_t)s * NCLASS + g * 4];
    float* p = &zout[(size_t)d * NCLASS + g * 4];
    asm volatile("red.global.add.v4.f32 [%0], {%1, %2, %3, %4};"
                 :: "l"(p), "f"(v * z.x), "f"(v * z.y), "f"(v * z.z), "f"(v * z.w)
                 : "memory");
}

// ---------------- log_softmax per row (one warp / row, in-place OK) ----------
__global__ void __launch_bounds__(256)
softmax_kernel(const float* __restrict__ z, float* __restrict__ out)
{
    int row = blockIdx.x * 8 + (threadIdx.x >> 5);
    int lane = threadIdx.x & 31;
    if (row >= N_NODES) return;
    const float* zr = z + (size_t)row * NCLASS;
    float v0 = zr[lane];
    bool has2 = (lane + 32) < NCLASS;
    float v1 = has2 ? zr[lane + 32] : -3.402823466e38f;
    float m = fmaxf(v0, v1);
    #pragma unroll
    for (int o = 16; o > 0; o >>= 1) m = fmaxf(m, __shfl_xor_sync(0xffffffffu, m, o));
    float s = __expf(v0 - m) + (has2 ? __expf(v1 - m) : 0.f);
    #pragma unroll
    for (int o = 16; o > 0; o >>= 1) s += __shfl_xor_sync(0xffffffffu, s, o);
    float lse = m + __logf(s);
    float* orow = out + (size_t)row * NCLASS;
    orow[lane] = v0 - lse;
    if (has2) orow[lane + 32] = v1 - lse;
}

// ---------------- launch ----------------
extern "C" void kernel_launch(void* const* d_in, const int* in_sizes, int n_in,
                              void* d_out, int out_size)
{
    const float* x     = (const float*)d_in[0];
    const int*   esrc  = (const int*)  d_in[1];
    const int*   edst  = (const int*)  d_in[2];
    const float* eval_ = (const float*)d_in[3];
    const float* W1    = (const float*)d_in[4];
    const float* b1    = (const float*)d_in[5];
    const float* W2    = (const float*)d_in[6];
    const float* b2    = (const float*)d_in[7];
    float* out = (float*)d_out;

    float *h, *h2, *za, *ev;
    cudaGetSymbolAddress((void**)&h,  g_h);
    cudaGetSymbolAddress((void**)&h2, g_h2);
    cudaGetSymbolAddress((void**)&za, g_za);
    cudaGetSymbolAddress((void**)&ev, g_ev);

    dim3 g1((N_NODES + 127) / 128, NHID / 128);   // (782, 2)
    gemm1_tf32_kernel<<<g1, 256>>>(x, W1, b1, h);
    gemm2_kernel<<<(N_NODES + 127) / 128, 256>>>(h, W2, b2, h2);
    edge_scale_kernel<<<(NEDGE / 4 + 255) / 256, 256>>>(eval_, ev);

    const int init_blocks = (N_NODES * NCLASS / 4 + 255) / 256;
    const int edge_blocks = (int)(((unsigned)NEDGE * 10u + 255u) / 256u);

    const float* zin = h2;
    for (int i = 0; i < KHOPS; i++) {
        float* zout = (i % 2 == 0) ? za : out;   // last iter (i=9) writes `out`
        scale_init_kernel<<<init_blocks, 256>>>(h2, zout);
        edge_kernel<<<edge_blocks, 256>>>(esrc, edst, ev, zin, zout);
        zin = zout;
    }

    softmax_kernel<<<(N_NODES + 7) / 8, 256>>>(out, out);
}

// round 5
// speedup vs baseline: 1.7619x; 1.1998x over previous
#include <cuda_runtime.h>
#include <cuda_bf16.h>
#include <cstdint>
#include <math.h>

#define N_NODES 100000
#define NFEAT   512
#define NHID    256
#define NCLASS  40
#define NEDGE   1600000
#define KHOPS   10
#define ALPHA_F 0.1f

// ---------------- scratch (device globals; no allocs allowed) ----------------
__device__ float g_h [(size_t)N_NODES * NHID];    // 102.4 MB
__device__ float g_h2[(size_t)N_NODES * NCLASS];  // 16 MB
__device__ float g_za[(size_t)N_NODES * NCLASS];  // 16 MB
__device__ int   g_deg[N_NODES];                  // degree histogram
__device__ int   g_rowptr[N_NODES + 1];           // CSR row pointers (by dst)
__device__ int   g_cursor[N_NODES];               // scatter cursors
__device__ int   g_csrc[NEDGE];                   // CSR src indices
__device__ float g_cev[NEDGE];                    // CSR edge vals (pre-scaled by 0.9)

// ---------------- cp.async helpers ----------------
__device__ __forceinline__ void cp_async16(uint32_t saddr, const void* gaddr) {
    asm volatile("cp.async.cg.shared.global [%0], [%1], 16;\n" :: "r"(saddr), "l"(gaddr));
}
__device__ __forceinline__ void cp_commit() {
    asm volatile("cp.async.commit_group;\n" ::: "memory");
}
__device__ __forceinline__ void cp_wait1() {
    asm volatile("cp.async.wait_group 1;\n" ::: "memory");
}

// ---------------- GEMM1: h = relu(x @ W1 + b1) via tf32 mma.sync -------------
#define G1_BK      16
#define G1_ASTRIDE 20
#define G1_BSTRIDE 136

__global__ void __launch_bounds__(256, 2)
gemm1_tf32_kernel(const float* __restrict__ x, const float* __restrict__ W1,
                  const float* __restrict__ b1, float* __restrict__ h)
{
    __shared__ float As[2][128][G1_ASTRIDE];
    __shared__ float Bs[2][G1_BK][G1_BSTRIDE];

    const int tid  = threadIdx.x;
    const int warp = tid >> 5;
    const int lane = tid & 31;
    const int grp  = lane >> 2;
    const int tig  = lane & 3;
    const int warp_m = warp & 1;
    const int warp_n = warp >> 1;

    const int m0 = blockIdx.x * 128;
    const int n0 = blockIdx.y * 128;

    const uint32_t sA = (uint32_t)__cvta_generic_to_shared(&As[0][0][0]);
    const uint32_t sB = (uint32_t)__cvta_generic_to_shared(&Bs[0][0][0]);

    float acc[4][4][4];
    #pragma unroll
    for (int i = 0; i < 4; i++)
        #pragma unroll
        for (int j = 0; j < 4; j++)
            #pragma unroll
            for (int r = 0; r < 4; r++) acc[i][j][r] = 0.f;

    const int ac0 = tid, ac1 = tid + 256;
    const int ar0 = ac0 >> 2, akc0 = (ac0 & 3) << 2;
    const int ar1 = ac1 >> 2, akc1 = (ac1 & 3) << 2;
    const int gr0 = min(m0 + ar0, N_NODES - 1);
    const int gr1 = min(m0 + ar1, N_NODES - 1);
    const int br0 = ac0 >> 5, bnc0 = (ac0 & 31) << 2;
    const int br1 = ac1 >> 5, bnc1 = (ac1 & 31) << 2;

    const int NT = NFEAT / G1_BK;  // 32

    {
        cp_async16(sA + (uint32_t)(((0*128 + ar0) * G1_ASTRIDE + akc0) * 4),
                   &x[(size_t)gr0 * NFEAT + akc0]);
        cp_async16(sA + (uint32_t)(((0*128 + ar1) * G1_ASTRIDE + akc1) * 4),
                   &x[(size_t)gr1 * NFEAT + akc1]);
        cp_async16(sB + (uint32_t)(((0*G1_BK + br0) * G1_BSTRIDE + bnc0) * 4),
                   &W1[(size_t)br0 * NHID + n0 + bnc0]);
        cp_async16(sB + (uint32_t)(((0*G1_BK + br1) * G1_BSTRIDE + bnc1) * 4),
                   &W1[(size_t)br1 * NHID + n0 + bnc1]);
        cp_commit();
    }

    for (int kt = 0; kt < NT; kt++) {
        if (kt + 1 < NT) {
            const int k0 = (kt + 1) * G1_BK;
            const int nb = (kt + 1) & 1;
            cp_async16(sA + (uint32_t)(((nb*128 + ar0) * G1_ASTRIDE + akc0) * 4),
                       &x[(size_t)gr0 * NFEAT + k0 + akc0]);
            cp_async16(sA + (uint32_t)(((nb*128 + ar1) * G1_ASTRIDE + akc1) * 4),
                       &x[(size_t)gr1 * NFEAT + k0 + akc1]);
            cp_async16(sB + (uint32_t)(((nb*G1_BK + br0) * G1_BSTRIDE + bnc0) * 4),
                       &W1[(size_t)(k0 + br0) * NHID + n0 + bnc0]);
            cp_async16(sB + (uint32_t)(((nb*G1_BK + br1) * G1_BSTRIDE + bnc1) * 4),
                       &W1[(size_t)(k0 + br1) * NHID + n0 + bnc1]);
        }
        cp_commit();
        cp_wait1();
        __syncthreads();

        const int buf = kt & 1;
        #pragma unroll
        for (int ks = 0; ks < 2; ks++) {
            const int kb = ks * 8;
            uint32_t a[4][4], b[4][2];
            #pragma unroll
            for (int mf = 0; mf < 4; mf++) {
                const int r = warp_m * 64 + mf * 16 + grp;
                a[mf][0] = __float_as_uint(As[buf][r    ][kb + tig    ]);
                a[mf][1] = __float_as_uint(As[buf][r + 8][kb + tig    ]);
                a[mf][2] = __float_as_uint(As[buf][r    ][kb + tig + 4]);
                a[mf][3] = __float_as_uint(As[buf][r + 8][kb + tig + 4]);
            }
            #pragma unroll
            for (int nf = 0; nf < 4; nf++) {
                const int cn = warp_n * 32 + nf * 8 + grp;
                b[nf][0] = __float_as_uint(Bs[buf][kb + tig    ][cn]);
                b[nf][1] = __float_as_uint(Bs[buf][kb + tig + 4][cn]);
            }
            #pragma unroll
            for (int mf = 0; mf < 4; mf++)
                #pragma unroll
                for (int nf = 0; nf < 4; nf++) {
                    asm volatile(
                        "mma.sync.aligned.m16n8k8.row.col.f32.tf32.tf32.f32 "
                        "{%0,%1,%2,%3}, {%4,%5,%6,%7}, {%8,%9}, {%0,%1,%2,%3};\n"
                        : "+f"(acc[mf][nf][0]), "+f"(acc[mf][nf][1]),
                          "+f"(acc[mf][nf][2]), "+f"(acc[mf][nf][3])
                        : "r"(a[mf][0]), "r"(a[mf][1]), "r"(a[mf][2]), "r"(a[mf][3]),
                          "r"(b[nf][0]), "r"(b[nf][1]));
                }
        }
        __syncthreads();
    }

    #pragma unroll
    for (int nf = 0; nf < 4; nf++) {
        const int cg = n0 + warp_n * 32 + nf * 8 + 2 * tig;
        const float bx = b1[cg], by = b1[cg + 1];
        #pragma unroll
        for (int mf = 0; mf < 4; mf++) {
            const int rg = m0 + warp_m * 64 + mf * 16 + grp;
            if (rg < N_NODES) {
                float2 o;
                o.x = fmaxf(acc[mf][nf][0] + bx, 0.f);
                o.y = fmaxf(acc[mf][nf][1] + by, 0.f);
                *(float2*)&h[(size_t)rg * NHID + cg] = o;
            }
            if (rg + 8 < N_NODES) {
                float2 o;
                o.x = fmaxf(acc[mf][nf][2] + bx, 0.f);
                o.y = fmaxf(acc[mf][nf][3] + by, 0.f);
                *(float2*)&h[(size_t)(rg + 8) * NHID + cg] = o;
            }
        }
    }
}

// ---------------- GEMM2: h2 = h @ W2 + b2, [100000,256]x[256,40] -------------
__global__ void __launch_bounds__(256, 2)
gemm2_kernel(const float* __restrict__ h, const float* __restrict__ W2,
             const float* __restrict__ b2, float* __restrict__ h2)
{
    __shared__ float hs[128][65];
    __shared__ float w2s[64][NCLASS];

    const int tid = threadIdx.x;
    const int r0 = blockIdx.x * 128;
    const int row = tid >> 1;
    const int half = tid & 1;

    float acc[20];
    #pragma unroll
    for (int j = 0; j < 20; j++) acc[j] = 0.f;

    for (int k0 = 0; k0 < NHID; k0 += 64) {
        #pragma unroll
        for (int i = 0; i < 8; i++) {
            int t = tid + i * 256;
            int rr = t >> 4;
            int cc = (t & 15) << 2;
            int gr = min(r0 + rr, N_NODES - 1);
            float4 v = *(const float4*)&h[(size_t)gr * NHID + k0 + cc];
            hs[rr][cc + 0] = v.x;
            hs[rr][cc + 1] = v.y;
            hs[rr][cc + 2] = v.z;
            hs[rr][cc + 3] = v.w;
        }
        for (int t = tid; t < 640; t += 256) {
            int wr = t / 10;
            int wc = (t - wr * 10) << 2;
            *(float4*)&w2s[wr][wc] = *(const float4*)&W2[(size_t)(k0 + wr) * NCLASS + wc];
        }
        __syncthreads();

        #pragma unroll 8
        for (int k = 0; k < 64; k++) {
            float hv = hs[row][k];
            #pragma unroll
            for (int j5 = 0; j5 < 5; j5++) {
                float4 w = *(const float4*)&w2s[k][half * 20 + j5 * 4];
                acc[j5 * 4 + 0] = fmaf(hv, w.x, acc[j5 * 4 + 0]);
                acc[j5 * 4 + 1] = fmaf(hv, w.y, acc[j5 * 4 + 1]);
                acc[j5 * 4 + 2] = fmaf(hv, w.z, acc[j5 * 4 + 2]);
                acc[j5 * 4 + 3] = fmaf(hv, w.w, acc[j5 * 4 + 3]);
            }
        }
        __syncthreads();
    }

    const int gr = r0 + row;
    if (gr < N_NODES) {
        #pragma unroll
        for (int j5 = 0; j5 < 5; j5++) {
            float4 o;
            o.x = acc[j5 * 4 + 0] + b2[half * 20 + j5 * 4 + 0];
            o.y = acc[j5 * 4 + 1] + b2[half * 20 + j5 * 4 + 1];
            o.z = acc[j5 * 4 + 2] + b2[half * 20 + j5 * 4 + 2];
            o.w = acc[j5 * 4 + 3] + b2[half * 20 + j5 * 4 + 3];
            *(float4*)&h2[(size_t)gr * NCLASS + half * 20 + j5 * 4] = o;
        }
    }
}

// ================= CSR build (by dst), rebuilt deterministically each call ===
__global__ void __launch_bounds__(256)
zero_deg_kernel(int* __restrict__ deg)
{
    int i = blockIdx.x * 256 + threadIdx.x;
    if (i < N_NODES) deg[i] = 0;
}

__global__ void __launch_bounds__(256)
hist_kernel(const int* __restrict__ edst, int* __restrict__ deg)
{
    int e = blockIdx.x * 256 + threadIdx.x;
    if (e < NEDGE) atomicAdd(&deg[edst[e]], 1);
}

// single-block scan: 1024 threads, 98 nodes each
__global__ void __launch_bounds__(1024)
scan_kernel(const int* __restrict__ deg, int* __restrict__ rowptr,
            int* __restrict__ cursor)
{
    __shared__ int part[1024];
    const int tid = threadIdx.x;
    const int CH = (N_NODES + 1023) / 1024;   // 98
    const int base = tid * CH;

    int s = 0;
    for (int i = 0; i < CH; i++) {
        int idx = base + i;
        if (idx < N_NODES) s += deg[idx];
    }
    part[tid] = s;
    __syncthreads();
    for (int off = 1; off < 1024; off <<= 1) {
        int v = (tid >= off) ? part[tid - off] : 0;
        __syncthreads();
        part[tid] += v;
        __syncthreads();
    }
    int run = (tid > 0) ? part[tid - 1] : 0;
    for (int i = 0; i < CH; i++) {
        int idx = base + i;
        if (idx < N_NODES) {
            rowptr[idx] = run;
            cursor[idx] = run;
            run += deg[idx];
        }
    }
    if (tid == 1023) rowptr[N_NODES] = run;
}

__global__ void __launch_bounds__(256)
scatter_kernel(const int* __restrict__ esrc, const int* __restrict__ edst,
               const float* __restrict__ eval_, int* __restrict__ cursor,
               int* __restrict__ csrc, float* __restrict__ cev)
{
    int e = blockIdx.x * 256 + threadIdx.x;
    if (e < NEDGE) {
        int d = edst[e];
        int slot = atomicAdd(&cursor[d], 1);
        csrc[slot] = esrc[e];
        cev[slot]  = (1.0f - ALPHA_F) * eval_[e];
    }
}

// ======== propagation hop: zout[dst] = alpha*h2[dst] + sum ev*zin[src] =======
// thread = (dst, class-group-of-4); 1M threads; no atomics, single store.
__global__ void __launch_bounds__(256)
prop_kernel(const int* __restrict__ rowptr, const int* __restrict__ csrc,
            const float* __restrict__ cev, const float* __restrict__ h2,
            const float* __restrict__ zin, float* __restrict__ zout)
{
    int idx = blockIdx.x * 256 + threadIdx.x;
    if (idx >= N_NODES * 10) return;
    int dst = idx / 10;
    int g = idx - dst * 10;
    const int col = g * 4;

    int e  = rowptr[dst];
    int e1 = rowptr[dst + 1];

    float4 hv = *(const float4*)&h2[(size_t)dst * NCLASS + col];
    float4 acc0 = make_float4(ALPHA_F * hv.x, ALPHA_F * hv.y,
                              ALPHA_F * hv.z, ALPHA_F * hv.w);
    float4 acc1 = make_float4(0.f, 0.f, 0.f, 0.f);

    for (; e + 2 <= e1; e += 2) {
        int sa = csrc[e],     sb = csrc[e + 1];
        float va = cev[e],    vb = cev[e + 1];
        float4 za = *(const float4*)&zin[(size_t)sa * NCLASS + col];
        float4 zb = *(const float4*)&zin[(size_t)sb * NCLASS + col];
        acc0.x = fmaf(va, za.x, acc0.x); acc0.y = fmaf(va, za.y, acc0.y);
        acc0.z = fmaf(va, za.z, acc0.z); acc0.w = fmaf(va, za.w, acc0.w);
        acc1.x = fmaf(vb, zb.x, acc1.x); acc1.y = fmaf(vb, zb.y, acc1.y);
        acc1.z = fmaf(vb, zb.z, acc1.z); acc1.w = fmaf(vb, zb.w, acc1.w);
    }
    if (e < e1) {
        int sa = csrc[e];
        float va = cev[e];
        float4 za = *(const float4*)&zin[(size_t)sa * NCLASS + col];
        acc0.x = fmaf(va, za.x, acc0.x); acc0.y = fmaf(va, za.y, acc0.y);
        acc0.z = fmaf(va, za.z, acc0.z); acc0.w = fmaf(va, za.w, acc0.w);
    }
    acc0.x += acc1.x; acc0.y += acc1.y; acc0.z += acc1.z; acc0.w += acc1.w;
    *(float4*)&zout[(size_t)dst * NCLASS + col] = acc0;
}

// ---------------- log_softmax per row (one warp / row, in-place OK) ----------
__global__ void __launch_bounds__(256)
softmax_kernel(const float* __restrict__ z, float* __restrict__ out)
{
    int row = blockIdx.x * 8 + (threadIdx.x >> 5);
    int lane = threadIdx.x & 31;
    if (row >= N_NODES) return;
    const float* zr = z + (size_t)row * NCLASS;
    float v0 = zr[lane];
    bool has2 = (lane + 32) < NCLASS;
    float v1 = has2 ? zr[lane + 32] : -3.402823466e38f;
    float m = fmaxf(v0, v1);
    #pragma unroll
    for (int o = 16; o > 0; o >>= 1) m = fmaxf(m, __shfl_xor_sync(0xffffffffu, m, o));
    float s = __expf(v0 - m) + (has2 ? __expf(v1 - m) : 0.f);
    #pragma unroll
    for (int o = 16; o > 0; o >>= 1) s += __shfl_xor_sync(0xffffffffu, s, o);
    float lse = m + __logf(s);
    float* orow = out + (size_t)row * NCLASS;
    orow[lane] = v0 - lse;
    if (has2) orow[lane + 32] = v1 - lse;
}

// ---------------- launch ----------------
extern "C" void kernel_launch(void* const* d_in, const int* in_sizes, int n_in,
                              void* d_out, int out_size)
{
    const float* x     = (const float*)d_in[0];
    const int*   esrc  = (const int*)  d_in[1];
    const int*   edst  = (const int*)  d_in[2];
    const float* eval_ = (const float*)d_in[3];
    const float* W1    = (const float*)d_in[4];
    const float* b1    = (const float*)d_in[5];
    const float* W2    = (const float*)d_in[6];
    const float* b2    = (const float*)d_in[7];
    float* out = (float*)d_out;

    float *h, *h2, *za, *cev;
    int *deg, *rowptr, *cursor, *csrc;
    cudaGetSymbolAddress((void**)&h,      g_h);
    cudaGetSymbolAddress((void**)&h2,     g_h2);
    cudaGetSymbolAddress((void**)&za,     g_za);
    cudaGetSymbolAddress((void**)&deg,    g_deg);
    cudaGetSymbolAddress((void**)&rowptr, g_rowptr);
    cudaGetSymbolAddress((void**)&cursor, g_cursor);
    cudaGetSymbolAddress((void**)&csrc,   g_csrc);
    cudaGetSymbolAddress((void**)&cev,    g_cev);

    dim3 g1((N_NODES + 127) / 128, NHID / 128);   // (782, 2)
    gemm1_tf32_kernel<<<g1, 256>>>(x, W1, b1, h);
    gemm2_kernel<<<(N_NODES + 127) / 128, 256>>>(h, W2, b2, h2);

    // CSR build (overlaps nothing; cheap)
    zero_deg_kernel<<<(N_NODES + 255) / 256, 256>>>(deg);
    hist_kernel<<<(NEDGE + 255) / 256, 256>>>(edst, deg);
    scan_kernel<<<1, 1024>>>(deg, rowptr, cursor);
    scatter_kernel<<<(NEDGE + 255) / 256, 256>>>(esrc, edst, eval_, cursor, csrc, cev);

    const int prop_blocks = (N_NODES * 10 + 255) / 256;
    const float* zin = h2;
    for (int i = 0; i < KHOPS; i++) {
        float* zout = (i % 2 == 0) ? za : out;   // last iter (i=9) writes `out`
        prop_kernel<<<prop_blocks, 256>>>(rowptr, csrc, cev, h2, zin, zout);
        zin = zout;
    }

    softmax_kernel<<<(N_NODES + 7) / 8, 256>>>(out, out);
}

// round 8
// speedup vs baseline: 1.8336x; 1.0407x over previous
#include <cuda_runtime.h>
#include <cuda_bf16.h>
#include <cstdint>
#include <math.h>

#define N_NODES 100000
#define NFEAT   512
#define NHID    256
#define NCLASS  40
#define NEDGE   1600000
#define KHOPS   10
#define ALPHA_F 0.1f

// ---------------- scratch (device globals; no allocs allowed) ----------------
__device__ float          g_h  [(size_t)N_NODES * NHID];   // 102.4 MB
__device__ float          g_h2 [(size_t)N_NODES * NCLASS]; // 16 MB
__device__ float          g_za [(size_t)N_NODES * NCLASS]; // 16 MB
__device__ __nv_bfloat16  g_xb [(size_t)N_NODES * NFEAT];  // 102.4 MB (bf16 x)
__device__ __nv_bfloat16  g_w1b[(size_t)NHID * NFEAT];     // 256 KB (W1^T bf16, [N][K])
__device__ int   g_deg[N_NODES];
__device__ int   g_rowptr[N_NODES + 1];
__device__ int   g_cursor[N_NODES];
__device__ int   g_csrc[NEDGE];
__device__ float g_cev[NEDGE];

// ---------------- cp.async helpers ----------------
__device__ __forceinline__ void cp_async16(uint32_t saddr, const void* gaddr) {
    asm volatile("cp.async.cg.shared.global [%0], [%1], 16;\n" :: "r"(saddr), "l"(gaddr));
}
__device__ __forceinline__ void cp_commit() {
    asm volatile("cp.async.commit_group;\n" ::: "memory");
}
__device__ __forceinline__ void cp_wait1() {
    asm volatile("cp.async.wait_group 1;\n" ::: "memory");
}

// ---------------- bf16 conversions ----------------
__global__ void __launch_bounds__(256)
conv_x_kernel(const float* __restrict__ x, __nv_bfloat16* __restrict__ xb)
{
    int i = blockIdx.x * 256 + threadIdx.x;         // per 8 floats
    const int n8 = N_NODES * NFEAT / 8;
    if (i < n8) {
        float4 a = ((const float4*)x)[2 * i];
        float4 b = ((const float4*)x)[2 * i + 1];
        __nv_bfloat162 p0 = __floats2bfloat162_rn(a.x, a.y);
        __nv_bfloat162 p1 = __floats2bfloat162_rn(a.z, a.w);
        __nv_bfloat162 p2 = __floats2bfloat162_rn(b.x, b.y);
        __nv_bfloat162 p3 = __floats2bfloat162_rn(b.z, b.w);
        uint4 o;
        o.x = *reinterpret_cast<unsigned*>(&p0);
        o.y = *reinterpret_cast<unsigned*>(&p1);
        o.z = *reinterpret_cast<unsigned*>(&p2);
        o.w = *reinterpret_cast<unsigned*>(&p3);
        ((uint4*)xb)[i] = o;
    }
}

__global__ void __launch_bounds__(256)
conv_w1_kernel(const float* __restrict__ W1, __nv_bfloat16* __restrict__ w1b)
{
    int id = blockIdx.x * 256 + threadIdx.x;        // (n,k), k fast
    if (id < NHID * NFEAT) {
        int n = id >> 9;
        int k = id & 511;
        w1b[id] = __float2bfloat16(W1[(size_t)k * NHID + n]);
    }
}

// ---------------- GEMM1: h = relu(x @ W1 + b1) via bf16 mma.sync -------------
// Block 128x128, BK=32 (bf16), 256 threads (8 warps 2x4, warp tile 64x32),
// double-buffered cp.async. A:[m][k] stride 40, B(=W1^T):[n][k] stride 40.
#define G1_BK  32
#define G1_STR 40   // elements; bank map (r*20 + tig) mod 32 -> conflict-free

__global__ void __launch_bounds__(256, 2)
gemm1_bf16_kernel(const __nv_bfloat16* __restrict__ xb,
                  const __nv_bfloat16* __restrict__ w1b,
                  const float* __restrict__ b1, float* __restrict__ h)
{
    __shared__ __nv_bfloat16 As[2][128][G1_STR];   // 20 KB
    __shared__ __nv_bfloat16 Bs[2][128][G1_STR];   // 20 KB

    const int tid  = threadIdx.x;
    const int warp = tid >> 5;
    const int lane = tid & 31;
    const int grp  = lane >> 2;   // 0..7
    const int tig  = lane & 3;    // 0..3
    const int warp_m = warp & 1;
    const int warp_n = warp >> 1;

    const int m0 = blockIdx.x * 128;
    const int n0 = blockIdx.y * 128;

    const uint32_t sA = (uint32_t)__cvta_generic_to_shared(&As[0][0][0]);
    const uint32_t sB = (uint32_t)__cvta_generic_to_shared(&Bs[0][0][0]);
    const uint32_t BUFB = 128u * G1_STR * 2u;      // bytes per buffer

    float acc[4][4][4];
    #pragma unroll
    for (int i = 0; i < 4; i++)
        #pragma unroll
        for (int j = 0; j < 4; j++)
            #pragma unroll
            for (int r = 0; r < 4; r++) acc[i][j][r] = 0.f;

    // loaders: per tile, A = 128 rows x 64B = 512 chunks; same for B; 2+2 per thread
    const int c0 = tid, c1 = tid + 256;
    const int ar0 = c0 >> 2, ak0 = (c0 & 3) * 8;   // element offset in row
    const int ar1 = c1 >> 2, ak1 = (c1 & 3) * 8;
    const int gr0 = min(m0 + ar0, N_NODES - 1);
    const int gr1 = min(m0 + ar1, N_NODES - 1);

    const int NT = NFEAT / G1_BK;  // 16

    auto load_tile = [&](int kt, int b) {
        const int kb = kt * G1_BK;
        const uint32_t ab = sA + (uint32_t)b * BUFB;
        const uint32_t bb = sB + (uint32_t)b * BUFB;
        cp_async16(ab + (uint32_t)((ar0 * G1_STR + ak0) * 2),
                   xb + (size_t)gr0 * NFEAT + kb + ak0);
        cp_async16(ab + (uint32_t)((ar1 * G1_STR + ak1) * 2),
                   xb + (size_t)gr1 * NFEAT + kb + ak1);
        cp_async16(bb + (uint32_t)((ar0 * G1_STR + ak0) * 2),
                   w1b + (size_t)(n0 + ar0) * NFEAT + kb + ak0);
        cp_async16(bb + (uint32_t)((ar1 * G1_STR + ak1) * 2),
                   w1b + (size_t)(n0 + ar1) * NFEAT + kb + ak1);
    };

    load_tile(0, 0);
    cp_commit();

    for (int kt = 0; kt < NT; kt++) {
        if (kt + 1 < NT) load_tile(kt + 1, (kt + 1) & 1);
        cp_commit();
        cp_wait1();          // tile kt resident
        __syncthreads();

        const int buf = kt & 1;
        #pragma unroll
        for (int ks = 0; ks < 2; ks++) {
            const int kb = ks * 16;
            uint32_t a[4][4], b[4][2];
            #pragma unroll
            for (int mf = 0; mf < 4; mf++) {
                const int r = warp_m * 64 + mf * 16 + grp;
                a[mf][0] = *(const uint32_t*)&As[buf][r    ][kb + tig * 2    ];
                a[mf][1] = *(const uint32_t*)&As[buf][r + 8][kb + tig * 2    ];
                a[mf][2] = *(const uint32_t*)&As[buf][r    ][kb + tig * 2 + 8];
                a[mf][3] = *(const uint32_t*)&As[buf][r + 8][kb + tig * 2 + 8];
            }
            #pragma unroll
            for (int nf = 0; nf < 4; nf++) {
                const int cn = warp_n * 32 + nf * 8 + grp;
                b[nf][0] = *(const uint32_t*)&Bs[buf][cn][kb + tig * 2    ];
                b[nf][1] = *(const uint32_t*)&Bs[buf][cn][kb + tig * 2 + 8];
            }
            #pragma unroll
            for (int mf = 0; mf < 4; mf++)
                #pragma unroll
                for (int nf = 0; nf < 4; nf++) {
                    asm volatile(
                        "mma.sync.aligned.m16n8k16.row.col.f32.bf16.bf16.f32 "
                        "{%0,%1,%2,%3}, {%4,%5,%6,%7}, {%8,%9}, {%0,%1,%2,%3};\n"
                        : "+f"(acc[mf][nf][0]), "+f"(acc[mf][nf][1]),
                          "+f"(acc[mf][nf][2]), "+f"(acc[mf][nf][3])
                        : "r"(a[mf][0]), "r"(a[mf][1]), "r"(a[mf][2]), "r"(a[mf][3]),
                          "r"(b[nf][0]), "r"(b[nf][1]));
                }
        }
        __syncthreads();
    }

    // epilogue: bias + relu, float2 stores
    #pragma unroll
    for (int nf = 0; nf < 4; nf++) {
        const int cg = n0 + warp_n * 32 + nf * 8 + 2 * tig;
        const float bx = b1[cg], by = b1[cg + 1];
        #pragma unroll
        for (int mf = 0; mf < 4; mf++) {
            const int rg = m0 + warp_m * 64 + mf * 16 + grp;
            if (rg < N_NODES) {
                float2 o;
                o.x = fmaxf(acc[mf][nf][0] + bx, 0.f);
                o.y = fmaxf(acc[mf][nf][1] + by, 0.f);
                *(float2*)&h[(size_t)rg * NHID + cg] = o;
            }
            if (rg + 8 < N_NODES) {
                float2 o;
                o.x = fmaxf(acc[mf][nf][2] + bx, 0.f);
                o.y = fmaxf(acc[mf][nf][3] + by, 0.f);
                *(float2*)&h[(size_t)(rg + 8) * NHID + cg] = o;
            }
        }
    }
}

// ---------------- GEMM2: h2 = h @ W2 + b2, [100000,256]x[256,40] -------------
__global__ void __launch_bounds__(256, 2)
gemm2_kernel(const float* __restrict__ h, const float* __restrict__ W2,
             const float* __restrict__ b2, float* __restrict__ h2)
{
    __shared__ float hs[128][65];
    __shared__ float w2s[64][NCLASS];

    const int tid = threadIdx.x;
    const int r0 = blockIdx.x * 128;
    const int row = tid >> 1;
    const int half = tid & 1;

    float acc[20];
    #pragma unroll
    for (int j = 0; j < 20; j++) acc[j] = 0.f;

    for (int k0 = 0; k0 < NHID; k0 += 64) {
        #pragma unroll
        for (int i = 0; i < 8; i++) {
            int t = tid + i * 256;
            int rr = t >> 4;
            int cc = (t & 15) << 2;
            int gr = min(r0 + rr, N_NODES - 1);
            float4 v = *(const float4*)&h[(size_t)gr * NHID + k0 + cc];
            hs[rr][cc + 0] = v.x;
            hs[rr][cc + 1] = v.y;
            hs[rr][cc + 2] = v.z;
            hs[rr][cc + 3] = v.w;
        }
        for (int t = tid; t < 640; t += 256) {
            int wr = t / 10;
            int wc = (t - wr * 10) << 2;
            *(float4*)&w2s[wr][wc] = *(const float4*)&W2[(size_t)(k0 + wr) * NCLASS + wc];
        }
        __syncthreads();

        #pragma unroll 8
        for (int k = 0; k < 64; k++) {
            float hv = hs[row][k];
            #pragma unroll
            for (int j5 = 0; j5 < 5; j5++) {
                float4 w = *(const float4*)&w2s[k][half * 20 + j5 * 4];
                acc[j5 * 4 + 0] = fmaf(hv, w.x, acc[j5 * 4 + 0]);
                acc[j5 * 4 + 1] = fmaf(hv, w.y, acc[j5 * 4 + 1]);
                acc[j5 * 4 + 2] = fmaf(hv, w.z, acc[j5 * 4 + 2]);
                acc[j5 * 4 + 3] = fmaf(hv, w.w, acc[j5 * 4 + 3]);
            }
        }
        __syncthreads();
    }

    const int gr = r0 + row;
    if (gr < N_NODES) {
        #pragma unroll
        for (int j5 = 0; j5 < 5; j5++) {
            float4 o;
            o.x = acc[j5 * 4 + 0] + b2[half * 20 + j5 * 4 + 0];
            o.y = acc[j5 * 4 + 1] + b2[half * 20 + j5 * 4 + 1];
            o.z = acc[j5 * 4 + 2] + b2[half * 20 + j5 * 4 + 2];
            o.w = acc[j5 * 4 + 3] + b2[half * 20 + j5 * 4 + 3];
            *(float4*)&h2[(size_t)gr * NCLASS + half * 20 + j5 * 4] = o;
        }
    }
}

// ================= CSR build (by dst), rebuilt deterministically each call ===
__global__ void __launch_bounds__(256)
zero_deg_kernel(int* __restrict__ deg)
{
    int i = blockIdx.x * 256 + threadIdx.x;
    if (i < N_NODES) deg[i] = 0;
}

__global__ void __launch_bounds__(256)
hist_kernel(const int* __restrict__ edst, int* __restrict__ deg)
{
    int e = blockIdx.x * 256 + threadIdx.x;
    if (e < NEDGE) atomicAdd(&deg[edst[e]], 1);
}

__global__ void __launch_bounds__(1024)
scan_kernel(const int* __restrict__ deg, int* __restrict__ rowptr,
            int* __restrict__ cursor)
{
    __shared__ int part[1024];
    const int tid = threadIdx.x;
    const int CH = (N_NODES + 1023) / 1024;   // 98
    const int base = tid * CH;

    int s = 0;
    for (int i = 0; i < CH; i++) {
        int idx = base + i;
        if (idx < N_NODES) s += deg[idx];
    }
    part[tid] = s;
    __syncthreads();
    for (int off = 1; off < 1024; off <<= 1) {
        int v = (tid >= off) ? part[tid - off] : 0;
        __syncthreads();
        part[tid] += v;
        __syncthreads();
    }
    int run = (tid > 0) ? part[tid - 1] : 0;
    for (int i = 0; i < CH; i++) {
        int idx = base + i;
        if (idx < N_NODES) {
            rowptr[idx] = run;
            cursor[idx] = run;
            run += deg[idx];
        }
    }
    if (tid == 1023) rowptr[N_NODES] = run;
}

__global__ void __launch_bounds__(256)
scatter_kernel(const int* __restrict__ esrc, const int* __restrict__ edst,
               const float* __restrict__ eval_, int* __restrict__ cursor,
               int* __restrict__ csrc, float* __restrict__ cev)
{
    int e = blockIdx.x * 256 + threadIdx.x;
    if (e < NEDGE) {
        int d = edst[e];
        int slot = atomicAdd(&cursor[d], 1);
        csrc[slot] = esrc[e];
        cev[slot]  = (1.0f - ALPHA_F) * eval_[e];
    }
}

// ======== propagation hop: zout[dst] = alpha*h2[dst] + sum ev*zin[src] =======
__global__ void __launch_bounds__(256)
prop_kernel(const int* __restrict__ rowptr, const int* __restrict__ csrc,
            const float* __restrict__ cev, const float* __restrict__ h2,
            const float* __restrict__ zin, float* __restrict__ zout)
{
    int idx = blockIdx.x * 256 + threadIdx.x;
    if (idx >= N_NODES * 10) return;
    int dst = idx / 10;
    int g = idx - dst * 10;
    const int col = g * 4;

    int e  = rowptr[dst];
    int e1 = rowptr[dst + 1];

    float4 hv = *(const float4*)&h2[(size_t)dst * NCLASS + col];
    float4 acc0 = make_float4(ALPHA_F * hv.x, ALPHA_F * hv.y,
                              ALPHA_F * hv.z, ALPHA_F * hv.w);
    float4 acc1 = make_float4(0.f, 0.f, 0.f, 0.f);

    for (; e + 2 <= e1; e += 2) {
        int sa = csrc[e],     sb = csrc[e + 1];
        float va = cev[e],    vb = cev[e + 1];
        float4 za = *(const float4*)&zin[(size_t)sa * NCLASS + col];
        float4 zb = *(const float4*)&zin[(size_t)sb * NCLASS + col];
        acc0.x = fmaf(va, za.x, acc0.x); acc0.y = fmaf(va, za.y, acc0.y);
        acc0.z = fmaf(va, za.z, acc0.z); acc0.w = fmaf(va, za.w, acc0.w);
        acc1.x = fmaf(vb, zb.x, acc1.x); acc1.y = fmaf(vb, zb.y, acc1.y);
        acc1.z = fmaf(vb, zb.z, acc1.z); acc1.w = fmaf(vb, zb.w, acc1.w);
    }
    if (e < e1) {
        int sa = csrc[e];
        float va = cev[e];
        float4 za = *(const float4*)&zin[(size_t)sa * NCLASS + col];
        acc0.x = fmaf(va, za.x, acc0.x); acc0.y = fmaf(va, za.y, acc0.y);
        acc0.z = fmaf(va, za.z, acc0.z); acc0.w = fmaf(va, za.w, acc0.w);
    }
    acc0.x += acc1.x; acc0.y += acc1.y; acc0.z += acc1.z; acc0.w += acc1.w;
    *(float4*)&zout[(size_t)dst * NCLASS + col] = acc0;
}

// ---------------- log_softmax per row ----------------
__global__ void __launch_bounds__(256)
softmax_kernel(const float* __restrict__ z, float* __restrict__ out)
{
    int row = blockIdx.x * 8 + (threadIdx.x >> 5);
    int lane = threadIdx.x & 31;
    if (row >= N_NODES) return;
    const float* zr = z + (size_t)row * NCLASS;
    float v0 = zr[lane];
    bool has2 = (lane + 32) < NCLASS;
    float v1 = has2 ? zr[lane + 32] : -3.402823466e38f;
    float m = fmaxf(v0, v1);
    #pragma unroll
    for (int o = 16; o > 0; o >>= 1) m = fmaxf(m, __shfl_xor_sync(0xffffffffu, m, o));
    float s = __expf(v0 - m) + (has2 ? __expf(v1 - m) : 0.f);
    #pragma unroll
    for (int o = 16; o > 0; o >>= 1) s += __shfl_xor_sync(0xffffffffu, s, o);
    float lse = m + __logf(s);
    float* orow = out + (size_t)row * NCLASS;
    orow[lane] = v0 - lse;
    if (has2) orow[lane + 32] = v1 - lse;
}

// ---------------- launch ----------------
extern "C" void kernel_launch(void* const* d_in, const int* in_sizes, int n_in,
                              void* d_out, int out_size)
{
    const float* x     = (const float*)d_in[0];
    const int*   esrc  = (const int*)  d_in[1];
    const int*   edst  = (const int*)  d_in[2];
    const float* eval_ = (const float*)d_in[3];
    const float* W1    = (const float*)d_in[4];
    const float* b1    = (const float*)d_in[5];
    const float* W2    = (const float*)d_in[6];
    const float* b2    = (const float*)d_in[7];
    float* out = (float*)d_out;

    float *h, *h2, *za, *cev;
    __nv_bfloat16 *xb, *w1b;
    int *deg, *rowptr, *cursor, *csrc;
    cudaGetSymbolAddress((void**)&h,      g_h);
    cudaGetSymbolAddress((void**)&h2,     g_h2);
    cudaGetSymbolAddress((void**)&za,     g_za);
    cudaGetSymbolAddress((void**)&xb,     g_xb);
    cudaGetSymbolAddress((void**)&w1b,    g_w1b);
    cudaGetSymbolAddress((void**)&deg,    g_deg);
    cudaGetSymbolAddress((void**)&rowptr, g_rowptr);
    cudaGetSymbolAddress((void**)&cursor, g_cursor);
    cudaGetSymbolAddress((void**)&csrc,   g_csrc);
    cudaGetSymbolAddress((void**)&cev,    g_cev);

    // bf16 conversions
    conv_x_kernel<<<(N_NODES * NFEAT / 8 + 255) / 256, 256>>>(x, xb);
    conv_w1_kernel<<<(NHID * NFEAT + 255) / 256, 256>>>(W1, w1b);

    // GEMM1 (bf16 mma.sync)
    dim3 g1((N_NODES + 127) / 128, NHID / 128);   // (782, 2)
    gemm1_bf16_kernel<<<g1, 256>>>(xb, w1b, b1, h);

    gemm2_kernel<<<(N_NODES + 127) / 128, 256>>>(h, W2, b2, h2);

    // CSR build
    zero_deg_kernel<<<(N_NODES + 255) / 256, 256>>>(deg);
    hist_kernel<<<(NEDGE + 255) / 256, 256>>>(edst, deg);
    scan_kernel<<<1, 1024>>>(deg, rowptr, cursor);
    scatter_kernel<<<(NEDGE + 255) / 256, 256>>>(esrc, edst, eval_, cursor, csrc, cev);

    const int prop_blocks = (N_NODES * 10 + 255) / 256;
    const float* zin = h2;
    for (int i = 0; i < KHOPS; i++) {
        float* zout = (i % 2 == 0) ? za : out;   // last iter (i=9) writes `out`
        prop_kernel<<<prop_blocks, 256>>>(rowptr, csrc, cev, h2, zin, zout);
        zin = zout;
    }

    softmax_kernel<<<(N_NODES + 7) / 8, 256>>>(out, out);
}

// round 9
// speedup vs baseline: 2.0567x; 1.1217x over previous
#include <cuda_runtime.h>
#include <cuda_bf16.h>
#include <cstdint>
#include <math.h>

#define N_NODES 100000
#define NFEAT   512
#define NHID    256
#define NCLASS  40
#define NEDGE   1600000
#define KHOPS   10
#define ALPHA_F 0.1f

// ---------------- scratch (device globals; no allocs allowed) ----------------
__device__ __nv_bfloat16  g_hb [(size_t)N_NODES * NHID];   // 51.2 MB (bf16 h)
__device__ float          g_h2 [(size_t)N_NODES * NCLASS]; // 16 MB
__device__ float          g_za [(size_t)N_NODES * NCLASS]; // 16 MB
__device__ __nv_bfloat16  g_xb [(size_t)N_NODES * NFEAT];  // 102.4 MB (bf16 x)
__device__ __nv_bfloat16  g_w1b[(size_t)NHID * NFEAT];     // 256 KB (W1^T bf16 [N][K])
__device__ __nv_bfloat16  g_w2t[(size_t)NCLASS * NHID];    // 20 KB (W2^T bf16 [N][K])
__device__ int   g_deg[N_NODES];
__device__ int   g_rowptr[N_NODES + 1];
__device__ int   g_cursor[N_NODES];
__device__ int   g_csrc[NEDGE];
__device__ float g_cev[NEDGE];

// ---------------- cp.async helpers ----------------
__device__ __forceinline__ void cp_async16(uint32_t saddr, const void* gaddr) {
    asm volatile("cp.async.cg.shared.global [%0], [%1], 16;\n" :: "r"(saddr), "l"(gaddr));
}
__device__ __forceinline__ void cp_commit() {
    asm volatile("cp.async.commit_group;\n" ::: "memory");
}
__device__ __forceinline__ void cp_wait1() {
    asm volatile("cp.async.wait_group 1;\n" ::: "memory");
}

// ---------------- bf16 conversions ----------------
__global__ void __launch_bounds__(256)
conv_x_kernel(const float* __restrict__ x, __nv_bfloat16* __restrict__ xb)
{
    int i = blockIdx.x * 256 + threadIdx.x;         // per 8 floats
    const int n8 = N_NODES * NFEAT / 8;
    if (i < n8) {
        float4 a = ((const float4*)x)[2 * i];
        float4 b = ((const float4*)x)[2 * i + 1];
        __nv_bfloat162 p0 = __floats2bfloat162_rn(a.x, a.y);
        __nv_bfloat162 p1 = __floats2bfloat162_rn(a.z, a.w);
        __nv_bfloat162 p2 = __floats2bfloat162_rn(b.x, b.y);
        __nv_bfloat162 p3 = __floats2bfloat162_rn(b.z, b.w);
        uint4 o;
        o.x = *reinterpret_cast<unsigned*>(&p0);
        o.y = *reinterpret_cast<unsigned*>(&p1);
        o.z = *reinterpret_cast<unsigned*>(&p2);
        o.w = *reinterpret_cast<unsigned*>(&p3);
        ((uint4*)xb)[i] = o;
    }
}

__global__ void __launch_bounds__(256)
conv_w1_kernel(const float* __restrict__ W1, __nv_bfloat16* __restrict__ w1b)
{
    int id = blockIdx.x * 256 + threadIdx.x;        // (n,k), k fast
    if (id < NHID * NFEAT) {
        int n = id >> 9;
        int k = id & 511;
        w1b[id] = __float2bfloat16(W1[(size_t)k * NHID + n]);
    }
}

__global__ void __launch_bounds__(256)
conv_w2_kernel(const float* __restrict__ W2, __nv_bfloat16* __restrict__ w2t)
{
    int id = blockIdx.x * 256 + threadIdx.x;        // (n,k), k fast
    if (id < NCLASS * NHID) {
        int n = id >> 8;
        int k = id & 255;
        w2t[id] = __float2bfloat16(W2[(size_t)k * NCLASS + n]);
    }
}

// ---------------- GEMM1: hb = relu(x @ W1 + b1) via bf16 mma.sync ------------
#define G1_BK  32
#define G1_STR 40

__global__ void __launch_bounds__(256, 2)
gemm1_bf16_kernel(const __nv_bfloat16* __restrict__ xb,
                  const __nv_bfloat16* __restrict__ w1b,
                  const float* __restrict__ b1, __nv_bfloat16* __restrict__ hb)
{
    __shared__ __nv_bfloat16 As[2][128][G1_STR];
    __shared__ __nv_bfloat16 Bs[2][128][G1_STR];

    const int tid  = threadIdx.x;
    const int warp = tid >> 5;
    const int lane = tid & 31;
    const int grp  = lane >> 2;
    const int tig  = lane & 3;
    const int warp_m = warp & 1;
    const int warp_n = warp >> 1;

    const int m0 = blockIdx.x * 128;
    const int n0 = blockIdx.y * 128;

    const uint32_t sA = (uint32_t)__cvta_generic_to_shared(&As[0][0][0]);
    const uint32_t sB = (uint32_t)__cvta_generic_to_shared(&Bs[0][0][0]);
    const uint32_t BUFB = 128u * G1_STR * 2u;

    float acc[4][4][4];
    #pragma unroll
    for (int i = 0; i < 4; i++)
        #pragma unroll
        for (int j = 0; j < 4; j++)
            #pragma unroll
            for (int r = 0; r < 4; r++) acc[i][j][r] = 0.f;

    const int c0 = tid, c1 = tid + 256;
    const int ar0 = c0 >> 2, ak0 = (c0 & 3) * 8;
    const int ar1 = c1 >> 2, ak1 = (c1 & 3) * 8;
    const int gr0 = min(m0 + ar0, N_NODES - 1);
    const int gr1 = min(m0 + ar1, N_NODES - 1);

    const int NT = NFEAT / G1_BK;  // 16

    auto load_tile = [&](int kt, int b) {
        const int kb = kt * G1_BK;
        const uint32_t ab = sA + (uint32_t)b * BUFB;
        const uint32_t bb = sB + (uint32_t)b * BUFB;
        cp_async16(ab + (uint32_t)((ar0 * G1_STR + ak0) * 2),
                   xb + (size_t)gr0 * NFEAT + kb + ak0);
        cp_async16(ab + (uint32_t)((ar1 * G1_STR + ak1) * 2),
                   xb + (size_t)gr1 * NFEAT + kb + ak1);
        cp_async16(bb + (uint32_t)((ar0 * G1_STR + ak0) * 2),
                   w1b + (size_t)(n0 + ar0) * NFEAT + kb + ak0);
        cp_async16(bb + (uint32_t)((ar1 * G1_STR + ak1) * 2),
                   w1b + (size_t)(n0 + ar1) * NFEAT + kb + ak1);
    };

    load_tile(0, 0);
    cp_commit();

    for (int kt = 0; kt < NT; kt++) {
        if (kt + 1 < NT) load_tile(kt + 1, (kt + 1) & 1);
        cp_commit();
        cp_wait1();
        __syncthreads();

        const int buf = kt & 1;
        #pragma unroll
        for (int ks = 0; ks < 2; ks++) {
            const int kb = ks * 16;
            uint32_t a[4][4], b[4][2];
            #pragma unroll
            for (int mf = 0; mf < 4; mf++) {
                const int r = warp_m * 64 + mf * 16 + grp;
                a[mf][0] = *(const uint32_t*)&As[buf][r    ][kb + tig * 2    ];
                a[mf][1] = *(const uint32_t*)&As[buf][r + 8][kb + tig * 2    ];
                a[mf][2] = *(const uint32_t*)&As[buf][r    ][kb + tig * 2 + 8];
                a[mf][3] = *(const uint32_t*)&As[buf][r + 8][kb + tig * 2 + 8];
            }
            #pragma unroll
            for (int nf = 0; nf < 4; nf++) {
                const int cn = warp_n * 32 + nf * 8 + grp;
                b[nf][0] = *(const uint32_t*)&Bs[buf][cn][kb + tig * 2    ];
                b[nf][1] = *(const uint32_t*)&Bs[buf][cn][kb + tig * 2 + 8];
            }
            #pragma unroll
            for (int mf = 0; mf < 4; mf++)
                #pragma unroll
                for (int nf = 0; nf < 4; nf++) {
                    asm volatile(
                        "mma.sync.aligned.m16n8k16.row.col.f32.bf16.bf16.f32 "
                        "{%0,%1,%2,%3}, {%4,%5,%6,%7}, {%8,%9}, {%0,%1,%2,%3};\n"
                        : "+f"(acc[mf][nf][0]), "+f"(acc[mf][nf][1]),
                          "+f"(acc[mf][nf][2]), "+f"(acc[mf][nf][3])
                        : "r"(a[mf][0]), "r"(a[mf][1]), "r"(a[mf][2]), "r"(a[mf][3]),
                          "r"(b[nf][0]), "r"(b[nf][1]));
                }
        }
        __syncthreads();
    }

    // epilogue: bias + relu, bf16x2 stores
    #pragma unroll
    for (int nf = 0; nf < 4; nf++) {
        const int cg = n0 + warp_n * 32 + nf * 8 + 2 * tig;
        const float bx = b1[cg], by = b1[cg + 1];
        #pragma unroll
        for (int mf = 0; mf < 4; mf++) {
            const int rg = m0 + warp_m * 64 + mf * 16 + grp;
            if (rg < N_NODES) {
                __nv_bfloat162 o = __floats2bfloat162_rn(
                    fmaxf(acc[mf][nf][0] + bx, 0.f),
                    fmaxf(acc[mf][nf][1] + by, 0.f));
                *(uint32_t*)&hb[(size_t)rg * NHID + cg] = *reinterpret_cast<uint32_t*>(&o);
            }
            if (rg + 8 < N_NODES) {
                __nv_bfloat162 o = __floats2bfloat162_rn(
                    fmaxf(acc[mf][nf][2] + bx, 0.f),
                    fmaxf(acc[mf][nf][3] + by, 0.f));
                *(uint32_t*)&hb[(size_t)(rg + 8) * NHID + cg] = *reinterpret_cast<uint32_t*>(&o);
            }
        }
    }
}

// ---------------- GEMM2: h2 = hb @ W2 + b2 via bf16 mma.sync -----------------
// Block 256 rows x 40 cols; 4 warps, warp tile 64x40 (4 m-frags x 5 n-frags).
// W2^T [40][264] resident whole in smem; A double-buffered [2][256][24], BK=16.
#define G2_ASTR 24
#define G2_BSTR 264

__global__ void __launch_bounds__(128)
gemm2_bf16_kernel(const __nv_bfloat16* __restrict__ hb,
                  const __nv_bfloat16* __restrict__ w2t,
                  const float* __restrict__ b2, float* __restrict__ h2)
{
    __shared__ __nv_bfloat16 As[2][256][G2_ASTR];  // 24.6 KB
    __shared__ __nv_bfloat16 Bs[NCLASS][G2_BSTR];  // 21.1 KB

    const int tid  = threadIdx.x;
    const int warp = tid >> 5;
    const int lane = tid & 31;
    const int grp  = lane >> 2;
    const int tig  = lane & 3;

    const int r0 = blockIdx.x * 256;

    const uint32_t sA = (uint32_t)__cvta_generic_to_shared(&As[0][0][0]);
    const uint32_t ABUF = 256u * G2_ASTR * 2u;

    // load whole W2^T into smem: 40*256 bf16 = 1280 x 8-elem chunks, 10/thread
    #pragma unroll
    for (int i = 0; i < 10; i++) {
        int c = tid + i * 128;
        int n = c >> 5;
        int ks = (c & 31) * 8;
        *(uint4*)&Bs[n][ks] = *(const uint4*)&w2t[(size_t)n * NHID + ks];
    }

    float acc[4][5][4];
    #pragma unroll
    for (int i = 0; i < 4; i++)
        #pragma unroll
        for (int j = 0; j < 5; j++)
            #pragma unroll
            for (int r = 0; r < 4; r++) acc[i][j][r] = 0.f;

    // A tile: 256 rows x 16 elems = 512 x 8-elem chunks, 4 per thread
    const int NT = NHID / 16;   // 16
    auto load_tile = [&](int kt, int b) {
        const uint32_t ab = sA + (uint32_t)b * ABUF;
        #pragma unroll
        for (int i = 0; i < 4; i++) {
            int c = tid + i * 128;
            int row = c >> 1;
            int seg = (c & 1) * 8;
            int gr = min(r0 + row, N_NODES - 1);
            cp_async16(ab + (uint32_t)((row * G2_ASTR + seg) * 2),
                       hb + (size_t)gr * NHID + kt * 16 + seg);
        }
    };

    load_tile(0, 0);
    cp_commit();
    __syncthreads();   // Bs ready too

    for (int kt = 0; kt < NT; kt++) {
        if (kt + 1 < NT) load_tile(kt + 1, (kt + 1) & 1);
        cp_commit();
        cp_wait1();
        __syncthreads();

        const int buf = kt & 1;
        uint32_t a[4][4], b[5][2];
        #pragma unroll
        for (int mf = 0; mf < 4; mf++) {
            const int r = warp * 64 + mf * 16 + grp;
            a[mf][0] = *(const uint32_t*)&As[buf][r    ][tig * 2    ];
            a[mf][1] = *(const uint32_t*)&As[buf][r + 8][tig * 2    ];
            a[mf][2] = *(const uint32_t*)&As[buf][r    ][tig * 2 + 8];
            a[mf][3] = *(const uint32_t*)&As[buf][r + 8][tig * 2 + 8];
        }
        #pragma unroll
        for (int nf = 0; nf < 5; nf++) {
            const int cn = nf * 8 + grp;
            b[nf][0] = *(const uint32_t*)&Bs[cn][kt * 16 + tig * 2    ];
            b[nf][1] = *(const uint32_t*)&Bs[cn][kt * 16 + tig * 2 + 8];
        }
        #pragma unroll
        for (int mf = 0; mf < 4; mf++)
            #pragma unroll
            for (int nf = 0; nf < 5; nf++) {
                asm volatile(
                    "mma.sync.aligned.m16n8k16.row.col.f32.bf16.bf16.f32 "
                    "{%0,%1,%2,%3}, {%4,%5,%6,%7}, {%8,%9}, {%0,%1,%2,%3};\n"
                    : "+f"(acc[mf][nf][0]), "+f"(acc[mf][nf][1]),
                      "+f"(acc[mf][nf][2]), "+f"(acc[mf][nf][3])
                    : "r"(a[mf][0]), "r"(a[mf][1]), "r"(a[mf][2]), "r"(a[mf][3]),
                      "r"(b[nf][0]), "r"(b[nf][1]));
            }
        __syncthreads();
    }

    // epilogue: bias, float2 stores (cols 0..39, all valid: nf*8+2*tig <= 38)
    #pragma unroll
    for (int nf = 0; nf < 5; nf++) {
        const int col = nf * 8 + 2 * tig;
        const float bx = b2[col], by = b2[col + 1];
        #pragma unroll
        for (int mf = 0; mf < 4; mf++) {
            const int rg = r0 + warp * 64 + mf * 16 + grp;
            if (rg < N_NODES) {
                float2 o;
                o.x = acc[mf][nf][0] + bx;
                o.y = acc[mf][nf][1] + by;
                *(float2*)&h2[(size_t)rg * NCLASS + col] = o;
            }
            if (rg + 8 < N_NODES) {
                float2 o;
                o.x = acc[mf][nf][2] + bx;
                o.y = acc[mf][nf][3] + by;
                *(float2*)&h2[(size_t)(rg + 8) * NCLASS + col] = o;
            }
        }
    }
}

// ================= CSR build (by dst), rebuilt deterministically each call ===
__global__ void __launch_bounds__(256)
zero_deg_kernel(int* __restrict__ deg)
{
    int i = blockIdx.x * 256 + threadIdx.x;
    if (i < N_NODES) deg[i] = 0;
}

__global__ void __launch_bounds__(256)
hist_kernel(const int* __restrict__ edst, int* __restrict__ deg)
{
    int e = blockIdx.x * 256 + threadIdx.x;
    if (e < NEDGE) atomicAdd(&deg[edst[e]], 1);
}

__global__ void __launch_bounds__(1024)
scan_kernel(const int* __restrict__ deg, int* __restrict__ rowptr,
            int* __restrict__ cursor)
{
    __shared__ int part[1024];
    const int tid = threadIdx.x;
    const int CH = (N_NODES + 1023) / 1024;   // 98
    const int base = tid * CH;

    int s = 0;
    for (int i = 0; i < CH; i++) {
        int idx = base + i;
        if (idx < N_NODES) s += deg[idx];
    }
    part[tid] = s;
    __syncthreads();
    for (int off = 1; off < 1024; off <<= 1) {
        int v = (tid >= off) ? part[tid - off] : 0;
        __syncthreads();
        part[tid] += v;
        __syncthreads();
    }
    int run = (tid > 0) ? part[tid - 1] : 0;
    for (int i = 0; i < CH; i++) {
        int idx = base + i;
        if (idx < N_NODES) {
            rowptr[idx] = run;
            cursor[idx] = run;
            run += deg[idx];
        }
    }
    if (tid == 1023) rowptr[N_NODES] = run;
}

__global__ void __launch_bounds__(256)
scatter_kernel(const int* __restrict__ esrc, const int* __restrict__ edst,
               const float* __restrict__ eval_, int* __restrict__ cursor,
               int* __restrict__ csrc, float* __restrict__ cev)
{
    int e = blockIdx.x * 256 + threadIdx.x;
    if (e < NEDGE) {
        int d = edst[e];
        int slot = atomicAdd(&cursor[d], 1);
        csrc[slot] = esrc[e];
        cev[slot]  = (1.0f - ALPHA_F) * eval_[e];
    }
}

// ======== propagation hop: zout[dst] = alpha*h2[dst] + sum ev*zin[src] =======
__global__ void __launch_bounds__(256)
prop_kernel(const int* __restrict__ rowptr, const int* __restrict__ csrc,
            const float* __restrict__ cev, const float* __restrict__ h2,
            const float* __restrict__ zin, float* __restrict__ zout)
{
    int idx = blockIdx.x * 256 + threadIdx.x;
    if (idx >= N_NODES * 10) return;
    int dst = idx / 10;
    int g = idx - dst * 10;
    const int col = g * 4;

    int e  = rowptr[dst];
    int e1 = rowptr[dst + 1];

    float4 hv = *(const float4*)&h2[(size_t)dst * NCLASS + col];
    float4 acc0 = make_float4(ALPHA_F * hv.x, ALPHA_F * hv.y,
                              ALPHA_F * hv.z, ALPHA_F * hv.w);
    float4 acc1 = make_float4(0.f, 0.f, 0.f, 0.f);

    for (; e + 2 <= e1; e += 2) {
        int sa = csrc[e],     sb = csrc[e + 1];
        float va = cev[e],    vb = cev[e + 1];
        float4 za = *(const float4*)&zin[(size_t)sa * NCLASS + col];
        float4 zb = *(const float4*)&zin[(size_t)sb * NCLASS + col];
        acc0.x = fmaf(va, za.x, acc0.x); acc0.y = fmaf(va, za.y, acc0.y);
        acc0.z = fmaf(va, za.z, acc0.z); acc0.w = fmaf(va, za.w, acc0.w);
        acc1.x = fmaf(vb, zb.x, acc1.x); acc1.y = fmaf(vb, zb.y, acc1.y);
        acc1.z = fmaf(vb, zb.z, acc1.z); acc1.w = fmaf(vb, zb.w, acc1.w);
    }
    if (e < e1) {
        int sa = csrc[e];
        float va = cev[e];
        float4 za = *(const float4*)&zin[(size_t)sa * NCLASS + col];
        acc0.x = fmaf(va, za.x, acc0.x); acc0.y = fmaf(va, za.y, acc0.y);
        acc0.z = fmaf(va, za.z, acc0.z); acc0.w = fmaf(va, za.w, acc0.w);
    }
    acc0.x += acc1.x; acc0.y += acc1.y; acc0.z += acc1.z; acc0.w += acc1.w;
    *(float4*)&zout[(size_t)dst * NCLASS + col] = acc0;
}

// ---------------- log_softmax per row ----------------
__global__ void __launch_bounds__(256)
softmax_kernel(const float* __restrict__ z, float* __restrict__ out)
{
    int row = blockIdx.x * 8 + (threadIdx.x >> 5);
    int lane = threadIdx.x & 31;
    if (row >= N_NODES) return;
    const float* zr = z + (size_t)row * NCLASS;
    float v0 = zr[lane];
    bool has2 = (lane + 32) < NCLASS;
    float v1 = has2 ? zr[lane + 32] : -3.402823466e38f;
    float m = fmaxf(v0, v1);
    #pragma unroll
    for (int o = 16; o > 0; o >>= 1) m = fmaxf(m, __shfl_xor_sync(0xffffffffu, m, o));
    float s = __expf(v0 - m) + (has2 ? __expf(v1 - m) : 0.f);
    #pragma unroll
    for (int o = 16; o > 0; o >>= 1) s += __shfl_xor_sync(0xffffffffu, s, o);
    float lse = m + __logf(s);
    float* orow = out + (size_t)row * NCLASS;
    orow[lane] = v0 - lse;
    if (has2) orow[lane + 32] = v1 - lse;
}

// ---------------- launch ----------------
extern "C" void kernel_launch(void* const* d_in, const int* in_sizes, int n_in,
                              void* d_out, int out_size)
{
    const float* x     = (const float*)d_in[0];
    const int*   esrc  = (const int*)  d_in[1];
    const int*   edst  = (const int*)  d_in[2];
    const float* eval_ = (const float*)d_in[3];
    const float* W1    = (const float*)d_in[4];
    const float* b1    = (const float*)d_in[5];
    const float* W2    = (const float*)d_in[6];
    const float* b2    = (const float*)d_in[7];
    float* out = (float*)d_out;

    float *h2, *za, *cev;
    __nv_bfloat16 *hb, *xb, *w1b, *w2t;
    int *deg, *rowptr, *cursor, *csrc;
    cudaGetSymbolAddress((void**)&hb,     g_hb);
    cudaGetSymbolAddress((void**)&h2,     g_h2);
    cudaGetSymbolAddress((void**)&za,     g_za);
    cudaGetSymbolAddress((void**)&xb,     g_xb);
    cudaGetSymbolAddress((void**)&w1b,    g_w1b);
    cudaGetSymbolAddress((void**)&w2t,    g_w2t);
    cudaGetSymbolAddress((void**)&deg,    g_deg);
    cudaGetSymbolAddress((void**)&rowptr, g_rowptr);
    cudaGetSymbolAddress((void**)&cursor, g_cursor);
    cudaGetSymbolAddress((void**)&csrc,   g_csrc);
    cudaGetSymbolAddress((void**)&cev,    g_cev);

    // bf16 conversions
    conv_x_kernel<<<(N_NODES * NFEAT / 8 + 255) / 256, 256>>>(x, xb);
    conv_w1_kernel<<<(NHID * NFEAT + 255) / 256, 256>>>(W1, w1b);
    conv_w2_kernel<<<(NCLASS * NHID + 255) / 256, 256>>>(W2, w2t);

    // GEMM1 (bf16 mma.sync) -> hb (bf16)
    dim3 g1((N_NODES + 127) / 128, NHID / 128);   // (782, 2)
    gemm1_bf16_kernel<<<g1, 256>>>(xb, w1b, b1, hb);

    // GEMM2 (bf16 mma.sync) -> h2 (fp32)
    gemm2_bf16_kernel<<<(N_NODES + 255) / 256, 128>>>(hb, w2t, b2, h2);

    // CSR build
    zero_deg_kernel<<<(N_NODES + 255) / 256, 256>>>(deg);
    hist_kernel<<<(NEDGE + 255) / 256, 256>>>(edst, deg);
    scan_kernel<<<1, 1024>>>(deg, rowptr, cursor);
    scatter_kernel<<<(NEDGE + 255) / 256, 256>>>(esrc, edst, eval_, cursor, csrc, cev);

    const int prop_blocks = (N_NODES * 10 + 255) / 256;
    const float* zin = h2;
    for (int i = 0; i < KHOPS; i++) {
        float* zout = (i % 2 == 0) ? za : out;   // last iter (i=9) writes `out`
        prop_kernel<<<prop_blocks, 256>>>(rowptr, csrc, cev, h2, zin, zout);
        zin = zout;
    }

    softmax_kernel<<<(N_NODES + 7) / 8, 256>>>(out, out);
}